// round 1
// baseline (speedup 1.0000x reference)
#include <cuda_runtime.h>
#include <cuda_bf16.h>
#include <math.h>

// Problem constants (Transformer_71957882077842)
#define LAYERS 8
#define HDIM   1024
#define KDIM   1024
#define IDIM   4096
#define VOCAB  32000
#define BATCH  2
#define SEQ    2048
#define MTOK   (BATCH * SEQ)   // 4096 tokens total

// ---------------- scratch (device globals; no cudaMalloc allowed) ----------
__device__ float g_x[(long)MTOK * HDIM];          // 16 MB  residual stream
__device__ float g_qkv[(long)MTOK * 3 * KDIM];    // 48 MB  fused qkv output
__device__ float g_scores[(long)BATCH * SEQ * SEQ]; // 32 MB attention scores
__device__ float g_o[(long)MTOK * KDIM];          // 16 MB  attn output
__device__ float g_h[(long)MTOK * IDIM];          // 64 MB  MLP hidden

// ---------------- embed gather --------------------------------------------
__global__ void embed_kernel(const int* __restrict__ tokens,
                             const float* __restrict__ emb,
                             float* __restrict__ x) {
    int i = blockIdx.x;                 // token index 0..MTOK-1
    int tok = tokens[i];
    const float4* src = (const float4*)(emb + (long)tok * HDIM);
    float4* dst = (float4*)(x + (long)i * HDIM);
    for (int c = threadIdx.x; c < HDIM / 4; c += blockDim.x) dst[c] = src[c];
}

// ---------------- causal softmax (in-place, with scale) --------------------
__global__ void softmax_causal(float* __restrict__ scores, float scale) {
    int row = blockIdx.x;               // b*SEQ + s
    int s = row & (SEQ - 1);
    float* p = scores + (long)row * SEQ;
    int tid = threadIdx.x;
    __shared__ float red[256];

    float m = -INFINITY;
    for (int t = tid; t <= s; t += blockDim.x) m = fmaxf(m, p[t] * scale);
    red[tid] = m; __syncthreads();
    for (int o = 128; o > 0; o >>= 1) {
        if (tid < o) red[tid] = fmaxf(red[tid], red[tid + o]);
        __syncthreads();
    }
    m = red[0]; __syncthreads();

    float sum = 0.f;
    for (int t = tid; t <= s; t += blockDim.x) {
        float e = __expf(p[t] * scale - m);
        p[t] = e;
        sum += e;
    }
    red[tid] = sum; __syncthreads();
    for (int o = 128; o > 0; o >>= 1) {
        if (tid < o) red[tid] += red[tid + o];
        __syncthreads();
    }
    float inv = 1.f / red[0];
    for (int t = tid; t <= s; t += blockDim.x) p[t] *= inv;
    for (int t = s + 1 + tid; t < SEQ; t += blockDim.x) p[t] = 0.f;
}

// ---------------- tiled SGEMM ----------------------------------------------
// C[M,N] = A[M,K] * B  (+ epilogue).  A row-major (lda), C row-major (ldc).
// TRANSB=false: B row-major [K,N] (ldb).  TRANSB=true: B row-major [N,K] (ldb),
// i.e. C = A * B^T (used for Q@K^T).
// EPI: 0 store, 1 +=C(residual in-place), 2 relu(.+bias), 3 +bias+C, 4 +bias
#define BM 128
#define BN 128
#define BK 8
#define TM 8
#define TN 8

template<int EPI, bool TRANSB>
__global__ __launch_bounds__(256)
void gemm_kernel(const float* __restrict__ A, const float* __restrict__ Bm,
                 float* __restrict__ C, const float* __restrict__ bias,
                 int Kd, int lda, int ldb, int ldc,
                 long bsA, long bsB, long bsC) {
    A  += (long)blockIdx.z * bsA;
    Bm += (long)blockIdx.z * bsB;
    C  += (long)blockIdx.z * bsC;

    __shared__ float As[BK][BM];
    __shared__ float Bs[BK][BN];

    const int tid = threadIdx.x;
    const int m0 = blockIdx.y * BM;
    const int n0 = blockIdx.x * BN;

    // transposed-load indices (A always; B when TRANSB)
    const int t_row = tid >> 1;            // 0..127
    const int t_k4  = (tid & 1) * 4;       // 0 or 4
    // direct-load indices (B when !TRANSB)
    const int b_row = tid >> 5;            // 0..7
    const int b_col = (tid & 31) * 4;      // 0..124

    const int tx = tid & 15, ty = tid >> 4;

    float acc[TM][TN];
    #pragma unroll
    for (int i = 0; i < TM; i++)
        #pragma unroll
        for (int j = 0; j < TN; j++) acc[i][j] = 0.f;

    for (int k0 = 0; k0 < Kd; k0 += BK) {
        float4 av = *(const float4*)(A + (long)(m0 + t_row) * lda + k0 + t_k4);
        As[t_k4 + 0][t_row] = av.x;
        As[t_k4 + 1][t_row] = av.y;
        As[t_k4 + 2][t_row] = av.z;
        As[t_k4 + 3][t_row] = av.w;
        if (TRANSB) {
            float4 bv = *(const float4*)(Bm + (long)(n0 + t_row) * ldb + k0 + t_k4);
            Bs[t_k4 + 0][t_row] = bv.x;
            Bs[t_k4 + 1][t_row] = bv.y;
            Bs[t_k4 + 2][t_row] = bv.z;
            Bs[t_k4 + 3][t_row] = bv.w;
        } else {
            float4 bv = *(const float4*)(Bm + (long)(k0 + b_row) * ldb + n0 + b_col);
            *(float4*)&Bs[b_row][b_col] = bv;
        }
        __syncthreads();

        #pragma unroll
        for (int k = 0; k < BK; k++) {
            float a[TM], b[TN];
            #pragma unroll
            for (int i = 0; i < TM; i++) a[i] = As[k][ty * TM + i];
            #pragma unroll
            for (int j = 0; j < TN; j++) b[j] = Bs[k][tx * TN + j];
            #pragma unroll
            for (int i = 0; i < TM; i++)
                #pragma unroll
                for (int j = 0; j < TN; j++) acc[i][j] = fmaf(a[i], b[j], acc[i][j]);
        }
        __syncthreads();
    }

    #pragma unroll
    for (int i = 0; i < TM; i++) {
        int m = m0 + ty * TM + i;
        #pragma unroll
        for (int j = 0; j < TN; j++) {
            int n = n0 + tx * TN + j;
            long idx = (long)m * ldc + n;
            float v = acc[i][j];
            if (EPI == 1) v += C[idx];
            if (EPI == 2) v = fmaxf(v + bias[n], 0.f);
            if (EPI == 3) v += bias[n] + C[idx];
            if (EPI == 4) v += bias[n];
            C[idx] = v;
        }
    }
}

// ---------------- host orchestration --------------------------------------
extern "C" void kernel_launch(void* const* d_in, const int* in_sizes, int n_in,
                              void* d_out, int out_size) {
    const int*   tokens    = (const int*)  d_in[0];
    const float* embedding = (const float*)d_in[1];
    const float* qkv_w     = (const float*)d_in[2];
    const float* o_w       = (const float*)d_in[3];
    const float* up_w      = (const float*)d_in[4];
    const float* up_b      = (const float*)d_in[5];
    const float* down_w    = (const float*)d_in[6];
    const float* down_b    = (const float*)d_in[7];
    const float* unemb_w   = (const float*)d_in[8];
    const float* unemb_b   = (const float*)d_in[9];
    float* logits = (float*)d_out;

    float *x, *qkvb, *scores, *o, *h;
    cudaGetSymbolAddress((void**)&x,      g_x);
    cudaGetSymbolAddress((void**)&qkvb,   g_qkv);
    cudaGetSymbolAddress((void**)&scores, g_scores);
    cudaGetSymbolAddress((void**)&o,      g_o);
    cudaGetSymbolAddress((void**)&h,      g_h);

    const float scale = 1.0f / sqrtf((float)KDIM);

    // 1. embed
    embed_kernel<<<MTOK, 256>>>(tokens, embedding, x);

    for (int l = 0; l < LAYERS; l++) {
        const float* wqkv = qkv_w  + (long)l * HDIM * 3 * KDIM;
        const float* wo   = o_w    + (long)l * KDIM * HDIM;
        const float* wu   = up_w   + (long)l * HDIM * IDIM;
        const float* bu   = up_b   + (long)l * IDIM;
        const float* wd   = down_w + (long)l * IDIM * HDIM;
        const float* bd   = down_b + (long)l * HDIM;

        // qkv: [4096,1024] x [1024,3072] -> g_qkv
        gemm_kernel<0, false><<<dim3(3 * KDIM / BN, MTOK / BM, 1), 256>>>(
            x, wqkv, qkvb, nullptr, HDIM, HDIM, 3 * KDIM, 3 * KDIM, 0, 0, 0);

        // scores = Q @ K^T per batch: [2048,1024] x [2048,1024]^T
        gemm_kernel<0, true><<<dim3(SEQ / BN, SEQ / BM, BATCH), 256>>>(
            qkvb,            /* Q at col 0   */
            qkvb + KDIM,     /* K at col KDIM */
            scores, nullptr, KDIM, 3 * KDIM, 3 * KDIM, SEQ,
            (long)SEQ * 3 * KDIM, (long)SEQ * 3 * KDIM, (long)SEQ * SEQ);

        // causal softmax (with scale folded in)
        softmax_causal<<<BATCH * SEQ, 256>>>(scores, scale);

        // o = attn @ V per batch: [2048,2048] x [2048,1024]
        gemm_kernel<0, false><<<dim3(KDIM / BN, SEQ / BM, BATCH), 256>>>(
            scores, qkvb + 2 * KDIM, o, nullptr, SEQ, SEQ, 3 * KDIM, KDIM,
            (long)SEQ * SEQ, (long)SEQ * 3 * KDIM, (long)SEQ * KDIM);

        // x += o @ Wo : [4096,1024] x [1024,1024]
        gemm_kernel<1, false><<<dim3(HDIM / BN, MTOK / BM, 1), 256>>>(
            o, wo, x, nullptr, KDIM, KDIM, HDIM, HDIM, 0, 0, 0);

        // h = relu(x @ Wu + bu) : [4096,1024] x [1024,4096]
        gemm_kernel<2, false><<<dim3(IDIM / BN, MTOK / BM, 1), 256>>>(
            x, wu, h, bu, HDIM, HDIM, IDIM, IDIM, 0, 0, 0);

        // x += h @ Wd + bd : [4096,4096] x [4096,1024]
        gemm_kernel<3, false><<<dim3(HDIM / BN, MTOK / BM, 1), 256>>>(
            h, wd, x, bd, IDIM, IDIM, HDIM, HDIM, 0, 0, 0);
    }

    // logits = x @ Wun + b : [4096,1024] x [1024,32000]
    gemm_kernel<4, false><<<dim3(VOCAB / BN, MTOK / BM, 1), 256>>>(
        x, unemb_w, logits, unemb_b, HDIM, HDIM, VOCAB, VOCAB, 0, 0, 0);
}